// round 7
// baseline (speedup 1.0000x reference)
#include <cuda_runtime.h>

#define HD 1024
#define WD 1024
#define OD 1016
#define SEG_OUT 32                 // output rows per warp-segment
#define NSEG    32                 // 32*32 = 1024 >= 1016 (last seg shifted up)
#define NSTRIP  9                  // 120 output cols per warp strip (lanes 1..30)
#define WPB     8                  // warps per block
// tasks = 16 * 9 * 32 = 4608 warps = 576 blocks; 4 blocks/SM * 148 = 592 -> 1 wave

static __device__ __forceinline__ float4 f4add(float4 a, float4 b) {
    return make_float4(a.x + b.x, a.y + b.y, a.z + b.z, a.w + b.w);
}
static __device__ __forceinline__ float4 f4sub(float4 a, float4 b) {
    return make_float4(a.x - b.x, a.y - b.y, a.z - b.z, a.w - b.w);
}
static __device__ __forceinline__ float4 ld4(const float* p) {
    return *reinterpret_cast<const float4*>(p);
}

// Horizontal 5-sum centered at each of this thread's 4 columns.
static __device__ __forceinline__ float4 hsum5(const float4 v) {
    const unsigned FULL = 0xffffffffu;
    float lm2 = __shfl_up_sync(FULL, v.z, 1);   // col 4l-2
    float lm1 = __shfl_up_sync(FULL, v.w, 1);   // col 4l-1
    float rp1 = __shfl_down_sync(FULL, v.x, 1); // col 4l+4
    float rp2 = __shfl_down_sync(FULL, v.y, 1); // col 4l+5
    float s012 = v.x + v.y + v.z;
    float4 h;
    h.x = lm2 + lm1 + s012;
    h.y = lm1 + s012 + v.w;
    h.z = s012 + v.w + rp1;
    h.w = (v.y + v.z) + (v.w + rp1) + rp2;
    return h;
}

__global__ void __launch_bounds__(256, 4)
cov_sliding(const float* __restrict__ xg, const float* __restrict__ yg,
            float* __restrict__ outg, int nbatch)
{
    const int warp = threadIdx.x >> 5;
    const int lane = threadIdx.x & 31;
    const int task = blockIdx.x * WPB + warp;
    const int total = nbatch * NSTRIP * NSEG;
    if (task >= total) return;

    const int seg   = task % NSEG;
    const int strip = (task / NSEG) % NSTRIP;
    const int b     = task / (NSEG * NSTRIP);

    const int gcol = strip * 120 + lane * 4;            // first input col this thread owns
    const int lcol = gcol > (WD - 4) ? (WD - 4) : gcol; // clamped load col (strip 8 edge)

    // Last segment is shifted up so loads never exceed row HD-1; it emits only
    // its exclusive rows via a raised t_emit (no duplicates, no clamps).
    const int s0_nom = seg * SEG_OUT;
    const int s0     = s0_nom > (OD - SEG_OUT) ? (OD - SEG_OUT) : s0_nom;  // <= 984
    const int t_emit = 8 + (s0_nom - s0);               // 8 normally, 16 for last seg

    const float* px = xg + (size_t)b * HD * WD + (size_t)s0 * WD + lcol;
    const float* py = yg + (size_t)b * HD * WD + (size_t)s0 * WD + lcol;

    const int  ocol = gcol - 4;
    const bool emit_lane = (lane >= 1) && (lane <= 30) && (ocol + 4 <= OD);
    float* po = outg + (size_t)b * OD * OD + (long)(s0 - 8) * OD + ocol;

    const float4 z4 = make_float4(0.f, 0.f, 0.f, 0.f);
    float4 vcx = z4, vcy = z4;         // vertical 5-row column sums of raw x / y
    float4 vsp = z4;                   // vertical 5-row sum of hp
    float4 hpr[5];                     // depth-5 ring of hp (hpr[t % 5])
#pragma unroll
    for (int i = 0; i < 5; ++i) hpr[i] = z4;

    const float inv25 = 1.0f / 25.0f;

    // ---- prologue: t = 0..3 (accumulate only) ----
#pragma unroll
    for (int t = 0; t < 4; ++t) {
        vcx = f4add(vcx, ld4(px));
        vcy = f4add(vcy, ld4(py));
        px += WD; py += WD; po += OD;
    }
    // ---- t = 4: first product row ----
    {
        const float4 xv = ld4(px);
        const float4 yv = ld4(py);
        const float4 xo = ld4(px - 2 * WD);
        const float4 yo = ld4(py - 2 * WD);
        vcx = f4add(vcx, xv);
        vcy = f4add(vcy, yv);
        const float4 mx = hsum5(vcx);
        const float4 my = hsum5(vcy);
        float4 p;
        p.x = (xo.x - mx.x * inv25) * (yo.x - my.x * inv25);
        p.y = (xo.y - mx.y * inv25) * (yo.y - my.y * inv25);
        p.z = (xo.z - mx.z * inv25) * (yo.z - my.z * inv25);
        p.w = (xo.w - mx.w * inv25) * (yo.w - my.w * inv25);
        const float4 hp = hsum5(p);
        vsp = f4add(vsp, hp);
        hpr[4] = hp;
        px += WD; py += WD; po += OD;
    }

    // ---- main: t = 5 .. 39 (7 groups of 5), uniform for all tasks ----
    for (int g = 0; g < 7; ++g) {
#pragma unroll
        for (int ph = 0; ph < 5; ++ph) {
            const int t = 5 + g * 5 + ph;

            const float4 xv  = ld4(px);
            const float4 yv  = ld4(py);
            const float4 xv5 = ld4(px - 5 * WD);   // L1 hit (loaded 5 rows ago)
            const float4 yv5 = ld4(py - 5 * WD);   // L1 hit
            const float4 xo  = ld4(px - 2 * WD);   // L1 hit
            const float4 yo  = ld4(py - 2 * WD);   // L1 hit

            vcx = f4add(vcx, f4sub(xv, xv5));      // rows t-4..t
            vcy = f4add(vcy, f4sub(yv, yv5));

            const float4 mx = hsum5(vcx);
            const float4 my = hsum5(vcy);

            float4 p;
            p.x = (xo.x - mx.x * inv25) * (yo.x - my.x * inv25);
            p.y = (xo.y - mx.y * inv25) * (yo.y - my.y * inv25);
            p.z = (xo.z - mx.z * inv25) * (yo.z - my.z * inv25);
            p.w = (xo.w - mx.w * inv25) * (yo.w - my.w * inv25);

            const float4 hp = hsum5(p);
            vsp = f4add(vsp, f4sub(hp, hpr[ph]));
            hpr[ph] = hp;

            if (t >= t_emit && emit_lane) {
                float4 o = make_float4(vsp.x * inv25, vsp.y * inv25,
                                       vsp.z * inv25, vsp.w * inv25);
                *reinterpret_cast<float4*>(po) = o;
            }
            px += WD; py += WD; po += OD;
        }
    }
}

extern "C" void kernel_launch(void* const* d_in, const int* in_sizes, int n_in,
                              void* d_out, int out_size)
{
    const float* x = (const float*)d_in[0];
    const float* y = (const float*)d_in[1];
    float* out = (float*)d_out;

    const int nbatch = in_sizes[0] / (HD * WD);         // 16
    const int total  = nbatch * NSTRIP * NSEG;          // 4608 warp-tasks
    const int blocks = (total + WPB - 1) / WPB;         // 576
    cov_sliding<<<blocks, WPB * 32>>>(x, y, out, nbatch);
}

// round 8
// speedup vs baseline: 1.1631x; 1.1631x over previous
#include <cuda_runtime.h>

#define HD 1024
#define WD 1024
#define OD 1016
#define SEG_OUT 47                 // output rows per warp-segment
#define NSEG    22                 // 22*47 = 1034 >= 1016 (last seg shifted up)
#define NSTRIP  9                  // 120 output cols per warp strip (lanes 1..30)
#define WPB     8                  // warps per block
// tasks = 16 * 9 * 22 = 3168 warps = 396 blocks; 3 blocks/SM * 148 = 444 -> all resident

static __device__ __forceinline__ float4 f4add(float4 a, float4 b) {
    return make_float4(a.x + b.x, a.y + b.y, a.z + b.z, a.w + b.w);
}
static __device__ __forceinline__ float4 f4sub(float4 a, float4 b) {
    return make_float4(a.x - b.x, a.y - b.y, a.z - b.z, a.w - b.w);
}
static __device__ __forceinline__ float4 ld4(const float* p) {
    return *reinterpret_cast<const float4*>(p);
}

// Horizontal 5-sum centered at each of this thread's 4 columns.
static __device__ __forceinline__ float4 hsum5(const float4 v) {
    const unsigned FULL = 0xffffffffu;
    float lm2 = __shfl_up_sync(FULL, v.z, 1);   // col 4l-2
    float lm1 = __shfl_up_sync(FULL, v.w, 1);   // col 4l-1
    float rp1 = __shfl_down_sync(FULL, v.x, 1); // col 4l+4
    float rp2 = __shfl_down_sync(FULL, v.y, 1); // col 4l+5
    float s012 = v.x + v.y + v.z;
    float4 h;
    h.x = lm2 + lm1 + s012;
    h.y = lm1 + s012 + v.w;
    h.z = s012 + v.w + rp1;
    h.w = (v.y + v.z) + (v.w + rp1) + rp2;
    return h;
}

__global__ void __launch_bounds__(256, 3)
cov_sliding(const float* __restrict__ xg, const float* __restrict__ yg,
            float* __restrict__ outg, int nbatch)
{
    const int warp = threadIdx.x >> 5;
    const int lane = threadIdx.x & 31;
    const int task = blockIdx.x * WPB + warp;
    const int total = nbatch * NSTRIP * NSEG;
    if (task >= total) return;

    const int seg   = task % NSEG;
    const int strip = (task / NSEG) % NSTRIP;
    const int b     = task / (NSEG * NSTRIP);

    const int gcol = strip * 120 + lane * 4;            // first input col this thread owns
    const int lcol = gcol > (WD - 4) ? (WD - 4) : gcol; // clamped load col (strip 8 edge)

    // Last segment shifted up so loads never exceed row HD-1; raised t_emit
    // keeps emitted rows exclusive. Max row touched = s0 + 54 <= 1023.
    const int s0_nom = seg * SEG_OUT;
    const int s0     = s0_nom > (OD - SEG_OUT) ? (OD - SEG_OUT) : s0_nom;  // <= 969
    const int t_emit = 8 + (s0_nom - s0);               // 8 normally, 26 for last seg

    // px/py point at the NEXT row to prefetch (row t+1 when computing row t).
    const float* px = xg + (size_t)b * HD * WD + (size_t)s0 * WD + lcol;
    const float* py = yg + (size_t)b * HD * WD + (size_t)s0 * WD + lcol;

    const int  ocol = gcol - 4;
    const bool emit_lane = (lane >= 1) && (lane <= 30) && (ocol + 4 <= OD);
    float* po = outg + (size_t)b * OD * OD + (long)(s0 - 8) * OD + ocol;

    const float4 z4 = make_float4(0.f, 0.f, 0.f, 0.f);
    float4 vcx = z4, vcy = z4;         // vertical 5-row column sums of raw x / y
    float4 vsp = z4;                   // vertical 5-row sum of hp
    float4 hpr[5];                     // depth-5 ring of hp (hpr[t % 5])
#pragma unroll
    for (int i = 0; i < 5; ++i) hpr[i] = z4;

    const float inv25 = 1.0f / 25.0f;

    // ---- prologue: rows 0..3 accumulate; prefetch row 4 ----
#pragma unroll
    for (int t = 0; t < 4; ++t) {
        vcx = f4add(vcx, ld4(px));
        vcy = f4add(vcy, ld4(py));
        px += WD; py += WD; po += OD;
    }
    float4 xv_cur = ld4(px);           // row 4
    float4 yv_cur = ld4(py);
    px += WD; py += WD;                // now point at row 5 (next to fetch)

    // ---- t = 4: first product row (px at row 5 => row t-2 = px - 3*WD) ----
    {
        const float4 xo = ld4(px - 3 * WD);
        const float4 yo = ld4(py - 3 * WD);
        vcx = f4add(vcx, xv_cur);
        vcy = f4add(vcy, yv_cur);
        const float4 mx = hsum5(vcx);
        const float4 my = hsum5(vcy);
        float4 p;
        p.x = (xo.x - mx.x * inv25) * (yo.x - my.x * inv25);
        p.y = (xo.y - mx.y * inv25) * (yo.y - my.y * inv25);
        p.z = (xo.z - mx.z * inv25) * (yo.z - my.z * inv25);
        p.w = (xo.w - mx.w * inv25) * (yo.w - my.w * inv25);
        const float4 hp = hsum5(p);
        vsp = f4add(vsp, hp);
        hpr[4] = hp;
        po += OD;
        xv_cur = ld4(px);              // prefetch row 5
        yv_cur = ld4(py);
        px += WD; py += WD;            // point at row 6
    }

    // ---- main: t = 5 .. 54 (10 groups of 5), uniform for all tasks ----
    // Invariant at phase top: xv_cur/yv_cur hold row t; px/py point at row t+1.
    for (int g = 0; g < 10; ++g) {
#pragma unroll
        for (int ph = 0; ph < 5; ++ph) {
            const int t = 5 + g * 5 + ph;

            // prefetch row t+1 (the only DRAM-missing loads) FIRST
            const float4 xv_nxt = ld4(px);
            const float4 yv_nxt = ld4(py);

            // L1-hit reloads: row t-5 = px - 6*WD, row t-2 = px - 3*WD
            const float4 xv5 = ld4(px - 6 * WD);
            const float4 yv5 = ld4(py - 6 * WD);
            const float4 xo  = ld4(px - 3 * WD);
            const float4 yo  = ld4(py - 3 * WD);

            vcx = f4add(vcx, f4sub(xv_cur, xv5));    // rows t-4..t
            vcy = f4add(vcy, f4sub(yv_cur, yv5));

            const float4 mx = hsum5(vcx);
            const float4 my = hsum5(vcy);

            float4 p;
            p.x = (xo.x - mx.x * inv25) * (yo.x - my.x * inv25);
            p.y = (xo.y - mx.y * inv25) * (yo.y - my.y * inv25);
            p.z = (xo.z - mx.z * inv25) * (yo.z - my.z * inv25);
            p.w = (xo.w - mx.w * inv25) * (yo.w - my.w * inv25);

            const float4 hp = hsum5(p);
            vsp = f4add(vsp, f4sub(hp, hpr[ph]));
            hpr[ph] = hp;

            if (t >= t_emit && emit_lane) {
                float4 o = make_float4(vsp.x * inv25, vsp.y * inv25,
                                       vsp.z * inv25, vsp.w * inv25);
                *reinterpret_cast<float4*>(po) = o;
            }

            xv_cur = xv_nxt; yv_cur = yv_nxt;        // rotate
            px += WD; py += WD; po += OD;
        }
    }
}

extern "C" void kernel_launch(void* const* d_in, const int* in_sizes, int n_in,
                              void* d_out, int out_size)
{
    const float* x = (const float*)d_in[0];
    const float* y = (const float*)d_in[1];
    float* out = (float*)d_out;

    const int nbatch = in_sizes[0] / (HD * WD);         // 16
    const int total  = nbatch * NSTRIP * NSEG;          // 3168 warp-tasks
    const int blocks = (total + WPB - 1) / WPB;         // 396
    cov_sliding<<<blocks, WPB * 32>>>(x, y, out, nbatch);
}

// round 9
// speedup vs baseline: 1.4397x; 1.2378x over previous
#include <cuda_runtime.h>

#define HD 1024
#define WD 1024
#define OD 1016
#define SEG_OUT 67                 // output rows per warp-segment
#define NSEG    16                 // 16*67 = 1072 >= 1016 (last seg shifted up)
#define NSTRIP  9                  // 120 output cols per warp strip (lanes 1..30)
#define WPB     4                  // warps per block (128 threads)
// tasks = 16 * 9 * 16 = 2304 warps = 576 blocks; 4 blocks/SM * 148 = 592 -> single wave

static __device__ __forceinline__ float4 f4add(float4 a, float4 b) {
    return make_float4(a.x + b.x, a.y + b.y, a.z + b.z, a.w + b.w);
}
static __device__ __forceinline__ float4 f4sub(float4 a, float4 b) {
    return make_float4(a.x - b.x, a.y - b.y, a.z - b.z, a.w - b.w);
}
static __device__ __forceinline__ float4 ld4(const float* p) {
    return *reinterpret_cast<const float4*>(p);
}

// Horizontal 5-sum centered at each of this thread's 4 columns.
static __device__ __forceinline__ float4 hsum5(const float4 v) {
    const unsigned FULL = 0xffffffffu;
    float lm2 = __shfl_up_sync(FULL, v.z, 1);   // col 4l-2
    float lm1 = __shfl_up_sync(FULL, v.w, 1);   // col 4l-1
    float rp1 = __shfl_down_sync(FULL, v.x, 1); // col 4l+4
    float rp2 = __shfl_down_sync(FULL, v.y, 1); // col 4l+5
    float s012 = v.x + v.y + v.z;
    float4 h;
    h.x = lm2 + lm1 + s012;
    h.y = lm1 + s012 + v.w;
    h.z = s012 + v.w + rp1;
    h.w = (v.y + v.z) + (v.w + rp1) + rp2;
    return h;
}

__global__ void __launch_bounds__(128, 4)
cov_sliding(const float* __restrict__ xg, const float* __restrict__ yg,
            float* __restrict__ outg, int nbatch)
{
    const int warp = threadIdx.x >> 5;
    const int lane = threadIdx.x & 31;
    const int task = blockIdx.x * WPB + warp;
    const int total = nbatch * NSTRIP * NSEG;
    if (task >= total) return;

    const int seg   = task % NSEG;
    const int strip = (task / NSEG) % NSTRIP;
    const int b     = task / (NSEG * NSTRIP);

    const int gcol = strip * 120 + lane * 4;            // first input col this thread owns
    const int lcol = gcol > (WD - 4) ? (WD - 4) : gcol; // clamped load col (strip 8 edge)

    // Last segment shifted up so loads never exceed row HD-1 (max touched row
    // = s0 + 74 <= 1023); raised t_emit keeps emitted rows exclusive.
    const int s0_nom = seg * SEG_OUT;
    const int s0     = s0_nom > (OD - SEG_OUT) ? (OD - SEG_OUT) : s0_nom;  // <= 949
    const int t_emit = 8 + (s0_nom - s0);               // 8 normally, 64 for last seg

    const float* px = xg + (size_t)b * HD * WD + (size_t)s0 * WD + lcol;
    const float* py = yg + (size_t)b * HD * WD + (size_t)s0 * WD + lcol;

    const int  ocol = gcol - 4;
    const bool emit_lane = (lane >= 1) && (lane <= 30) && (ocol + 4 <= OD);
    float* po = outg + (size_t)b * OD * OD + (long)(s0 - 8) * OD + ocol;

    const float4 z4 = make_float4(0.f, 0.f, 0.f, 0.f);
    float4 vcx = z4, vcy = z4;         // vertical 5-row column sums of raw x / y
    float4 vsp = z4;                   // vertical 5-row sum of hp
    float4 hpr[5];                     // depth-5 ring of hp (slot = t mod 5)
#pragma unroll
    for (int i = 0; i < 5; ++i) hpr[i] = z4;

    const float inv25 = 1.0f / 25.0f;

    // ---- prologue rows 0..3: accumulate only ----
#pragma unroll
    for (int t = 0; t < 4; ++t) {
        vcx = f4add(vcx, ld4(px));
        vcy = f4add(vcy, ld4(py));
        px += WD; py += WD; po += OD;
    }
    // ---- t = 4: first product row (slot 4) ----
    {
        const float4 xv = ld4(px);
        const float4 yv = ld4(py);
        px += WD; py += WD; po += OD;                   // px -> row 5
        const float4 xo = ld4(px - 3 * WD);             // row 2
        const float4 yo = ld4(py - 3 * WD);
        vcx = f4add(vcx, xv);
        vcy = f4add(vcy, yv);
        const float4 mx = hsum5(vcx);
        const float4 my = hsum5(vcy);
        float4 p;
        p.x = (xo.x - mx.x * inv25) * (yo.x - my.x * inv25);
        p.y = (xo.y - mx.y * inv25) * (yo.y - my.y * inv25);
        p.z = (xo.z - mx.z * inv25) * (yo.z - my.z * inv25);
        p.w = (xo.w - mx.w * inv25) * (yo.w - my.w * inv25);
        const float4 hp = hsum5(p);
        vsp = hp;
        hpr[4] = hp;
    }

    // Preload first pair (rows 5,6); px -> row 7
    float4 xvA = ld4(px), xvB = ld4(px + WD);
    float4 yvA = ld4(py), yvB = ld4(py + WD);
    px += 2 * WD; py += 2 * WD;

    // ---- main: 7 groups x 5 pairs, rows t = 5..74 ----
    // Invariant at pair top: xvA/yvA = row t, xvB/yvB = row t+1, px -> row t+2,
    // po -> output row (s0 + t - 8).
    for (int g = 0; g < 7; ++g) {
#pragma unroll
        for (int j = 0; j < 5; ++j) {
            const int tA = 5 + g * 10 + 2 * j;
            const int sA = (2 * j) % 5;                 // tA mod 5 (compile-time)
            const int sB = (2 * j + 1) % 5;

            // prefetch next pair (rows t+2, t+3) — the only DRAM-missing loads
            const float4 xvA_n = ld4(px), xvB_n = ld4(px + WD);
            const float4 yvA_n = ld4(py), yvB_n = ld4(py + WD);

            // L1-hit reloads (relative to px = row t+2):
            const float4 xv5A = ld4(px - 7 * WD);       // row t-5
            const float4 xv5B = ld4(px - 6 * WD);       // row t-4
            const float4 yv5A = ld4(py - 7 * WD);
            const float4 yv5B = ld4(py - 6 * WD);
            const float4 xoA  = ld4(px - 4 * WD);       // row t-2
            const float4 xoB  = ld4(px - 3 * WD);       // row t-1
            const float4 yoA  = ld4(py - 4 * WD);
            const float4 yoB  = ld4(py - 3 * WD);

            // vertical column sums for rows t and t+1 (two short serial adds)
            const float4 vcx1 = f4add(vcx, f4sub(xvA, xv5A));   // rows t-4..t
            const float4 vcy1 = f4add(vcy, f4sub(yvA, yv5A));
            const float4 vcx2 = f4add(vcx1, f4sub(xvB, xv5B));  // rows t-3..t+1
            const float4 vcy2 = f4add(vcy1, f4sub(yvB, yv5B));

            // two independent hsum->p->hsum chains
            const float4 mxA = hsum5(vcx1);
            const float4 myA = hsum5(vcy1);
            const float4 mxB = hsum5(vcx2);
            const float4 myB = hsum5(vcy2);

            float4 pA, pB;
            pA.x = (xoA.x - mxA.x * inv25) * (yoA.x - myA.x * inv25);
            pA.y = (xoA.y - mxA.y * inv25) * (yoA.y - myA.y * inv25);
            pA.z = (xoA.z - mxA.z * inv25) * (yoA.z - myA.z * inv25);
            pA.w = (xoA.w - mxA.w * inv25) * (yoA.w - myA.w * inv25);
            pB.x = (xoB.x - mxB.x * inv25) * (yoB.x - myB.x * inv25);
            pB.y = (xoB.y - mxB.y * inv25) * (yoB.y - myB.y * inv25);
            pB.z = (xoB.z - mxB.z * inv25) * (yoB.z - myB.z * inv25);
            pB.w = (xoB.w - mxB.w * inv25) * (yoB.w - myB.w * inv25);

            const float4 hpA = hsum5(pA);
            const float4 hpB = hsum5(pB);

            const float4 vsp1 = f4add(vsp, f4sub(hpA, hpr[sA]));
            hpr[sA] = hpA;
            if (tA >= t_emit && emit_lane) {
                *reinterpret_cast<float4*>(po) =
                    make_float4(vsp1.x * inv25, vsp1.y * inv25,
                                vsp1.z * inv25, vsp1.w * inv25);
            }
            const float4 vsp2 = f4add(vsp1, f4sub(hpB, hpr[sB]));
            hpr[sB] = hpB;
            if (tA + 1 >= t_emit && emit_lane) {
                *reinterpret_cast<float4*>(po + OD) =
                    make_float4(vsp2.x * inv25, vsp2.y * inv25,
                                vsp2.z * inv25, vsp2.w * inv25);
            }

            vcx = vcx2; vcy = vcy2; vsp = vsp2;
            xvA = xvA_n; xvB = xvB_n; yvA = yvA_n; yvB = yvB_n;
            px += 2 * WD; py += 2 * WD; po += 2 * OD;
        }
    }
}

extern "C" void kernel_launch(void* const* d_in, const int* in_sizes, int n_in,
                              void* d_out, int out_size)
{
    const float* x = (const float*)d_in[0];
    const float* y = (const float*)d_in[1];
    float* out = (float*)d_out;

    const int nbatch = in_sizes[0] / (HD * WD);         // 16
    const int total  = nbatch * NSTRIP * NSEG;          // 2304 warp-tasks
    const int blocks = (total + WPB - 1) / WPB;         // 576
    cov_sliding<<<blocks, WPB * 32>>>(x, y, out, nbatch);
}